// round 1
// baseline (speedup 1.0000x reference)
#include <cuda_runtime.h>
#include <math.h>

#define EPSV 1e-5f

// Problem constants
constexpr int Bb  = 8;
constexpr int Cc  = 64;
constexpr int Tt  = 1000;
constexpr int Ff  = 64;
constexpr int Hh  = 4;
constexpr int HSs = 4;
constexpr int CVv = 16;
constexpr int Dd  = HSs * Ff;   // 256
constexpr int DV  = CVv * Ff;   // 1024
constexpr int HB  = Hh * Bb;    // 32

// Static device scratch (no allocations allowed)
__device__ float g_Q[HB * Tt * Dd];        // 8.192M floats
__device__ float g_K[HB * Tt * Dd];        // 8.192M floats
__device__ float g_V[HB * Tt * DV];        // 32.768M floats
__device__ float g_P[HB * Tt * Tt];        // 32.0M floats
__device__ float g_A[HB * Tt * DV];        // 32.768M floats

// ---------------------------------------------------------------------------
// group reduce: sum & sumsq over 64-thread group (2 aligned warps)
// ---------------------------------------------------------------------------
__device__ __forceinline__ void group_reduce64(float& s, float& ss, int tid,
                                               float* reds, float* redss) {
    #pragma unroll
    for (int o = 16; o > 0; o >>= 1) {
        s  += __shfl_xor_sync(0xffffffffu, s,  o);
        ss += __shfl_xor_sync(0xffffffffu, ss, o);
    }
    int warp = tid >> 5;
    if ((tid & 31) == 0) { reds[warp] = s; redss[warp] = ss; }
    __syncthreads();
    int h = tid >> 6;
    s  = reds[2 * h]  + reds[2 * h + 1];
    ss = redss[2 * h] + redss[2 * h + 1];
    __syncthreads();   // allow buffer reuse
}

// ---------------------------------------------------------------------------
// Kernel 1: QKV 1x1 conv + bias + PReLU + ChanFreqNorm, write attention layouts
// block = one (b, t); 256 threads: tid -> (h = tid>>6, f = tid&63)
// ---------------------------------------------------------------------------
__global__ void __launch_bounds__(256) qkv_kernel(
    const float* __restrict__ x,
    const float* __restrict__ qw, const float* __restrict__ qb,
    const float* __restrict__ qa, const float* __restrict__ qg,
    const float* __restrict__ qbe,
    const float* __restrict__ kw, const float* __restrict__ kb,
    const float* __restrict__ ka, const float* __restrict__ kg,
    const float* __restrict__ kbe,
    const float* __restrict__ vw, const float* __restrict__ vb,
    const float* __restrict__ va, const float* __restrict__ vg,
    const float* __restrict__ vbe)
{
    __shared__ float xs[Cc * Ff];            // 4096
    __shared__ float qws[Hh * HSs * Cc];     // 1024
    __shared__ float kws[Hh * HSs * Cc];     // 1024
    __shared__ float vws[Hh * CVv * Cc];     // 4096
    __shared__ float reds[8], redss[8];

    int bid = blockIdx.x;
    int b = bid / Tt, t = bid % Tt;
    int tid = threadIdx.x;

    // load x[b, :, t, :]  (coalesced over f)
    for (int i = tid; i < Cc * Ff; i += 256) {
        int c = i >> 6, f = i & 63;
        xs[i] = x[(((size_t)b * Cc + c) * Tt + t) * Ff + f];
    }
    for (int i = tid; i < Hh * HSs * Cc; i += 256) { qws[i] = qw[i]; kws[i] = kw[i]; }
    for (int i = tid; i < Hh * CVv * Cc; i += 256) vws[i] = vw[i];
    __syncthreads();

    int h = tid >> 6, f = tid & 63;

    float qv[HSs], kv[HSs], vv[CVv];
    #pragma unroll
    for (int i = 0; i < HSs; i++) { qv[i] = 0.f; kv[i] = 0.f; }
    #pragma unroll
    for (int i = 0; i < CVv; i++) vv[i] = 0.f;

    for (int c = 0; c < Cc; c++) {
        float xv = xs[c * Ff + f];
        #pragma unroll
        for (int i = 0; i < HSs; i++) {
            qv[i] = fmaf(qws[(h * HSs + i) * Cc + c], xv, qv[i]);
            kv[i] = fmaf(kws[(h * HSs + i) * Cc + c], xv, kv[i]);
        }
        #pragma unroll
        for (int i = 0; i < CVv; i++)
            vv[i] = fmaf(vws[(h * CVv + i) * Cc + c], xv, vv[i]);
    }

    int hb = h * Bb + b;

    // ----- Q branch: bias + prelu + norm over (HS,F)=256 -----
    {
        float alpha = qa[h];
        float s = 0.f, ss = 0.f;
        #pragma unroll
        for (int i = 0; i < HSs; i++) {
            float y = qv[i] + qb[h * HSs + i];
            y = y > 0.f ? y : alpha * y;
            qv[i] = y;
            s += y; ss += y * y;
        }
        group_reduce64(s, ss, tid, reds, redss);
        float mu  = s * (1.f / (HSs * Ff));
        float var = ss * (1.f / (HSs * Ff)) - mu * mu;
        float inv = 1.f / (sqrtf(fmaxf(var, 0.f)) + EPSV);
        size_t base = ((size_t)hb * Tt + t) * Dd;
        #pragma unroll
        for (int i = 0; i < HSs; i++) {
            int gi = (h * HSs + i) * Ff + f;
            g_Q[base + i * Ff + f] = (qv[i] - mu) * inv * qg[gi] + qbe[gi];
        }
    }

    // ----- K branch -----
    {
        float alpha = ka[h];
        float s = 0.f, ss = 0.f;
        #pragma unroll
        for (int i = 0; i < HSs; i++) {
            float y = kv[i] + kb[h * HSs + i];
            y = y > 0.f ? y : alpha * y;
            kv[i] = y;
            s += y; ss += y * y;
        }
        group_reduce64(s, ss, tid, reds, redss);
        float mu  = s * (1.f / (HSs * Ff));
        float var = ss * (1.f / (HSs * Ff)) - mu * mu;
        float inv = 1.f / (sqrtf(fmaxf(var, 0.f)) + EPSV);
        size_t base = ((size_t)hb * Tt + t) * Dd;
        #pragma unroll
        for (int i = 0; i < HSs; i++) {
            int gi = (h * HSs + i) * Ff + f;
            g_K[base + i * Ff + f] = (kv[i] - mu) * inv * kg[gi] + kbe[gi];
        }
    }

    // ----- V branch: norm over (CV,F)=1024 -----
    {
        float alpha = va[h];
        float s = 0.f, ss = 0.f;
        #pragma unroll
        for (int i = 0; i < CVv; i++) {
            float y = vv[i] + vb[h * CVv + i];
            y = y > 0.f ? y : alpha * y;
            vv[i] = y;
            s += y; ss += y * y;
        }
        group_reduce64(s, ss, tid, reds, redss);
        float mu  = s * (1.f / (CVv * Ff));
        float var = ss * (1.f / (CVv * Ff)) - mu * mu;
        float inv = 1.f / (sqrtf(fmaxf(var, 0.f)) + EPSV);
        size_t base = ((size_t)hb * Tt + t) * DV;
        #pragma unroll
        for (int i = 0; i < CVv; i++) {
            int gi = (h * CVv + i) * Ff + f;
            g_V[base + i * Ff + f] = (vv[i] - mu) * inv * vg[gi] + vbe[gi];
        }
    }
}

// ---------------------------------------------------------------------------
// Kernel 2: scores = (Q @ K^T) * 0.0625, batched over hb
// 128x128 tile, BK=16, 256 threads, 8x8 per thread
// ---------------------------------------------------------------------------
__global__ void __launch_bounds__(256) gemm_qk_kernel()
{
    __shared__ float As[16][132];
    __shared__ float Bs[16][132];

    int hb = blockIdx.z;
    int m0 = blockIdx.y * 128;
    int n0 = blockIdx.x * 128;
    int tid = threadIdx.x;
    int tx = tid & 15, ty = tid >> 4;

    const float* __restrict__ Ag = g_Q + (size_t)hb * Tt * Dd;
    const float* __restrict__ Bg = g_K + (size_t)hb * Tt * Dd;

    float acc[8][8];
    #pragma unroll
    for (int i = 0; i < 8; i++)
        #pragma unroll
        for (int j = 0; j < 8; j++) acc[i][j] = 0.f;

    for (int k0 = 0; k0 < Dd; k0 += 16) {
        #pragma unroll
        for (int l = 0; l < 2; l++) {
            int idx = tid + l * 256;          // 0..511
            int row = idx >> 2, q = idx & 3;
            float4 va = make_float4(0.f, 0.f, 0.f, 0.f);
            float4 vb = make_float4(0.f, 0.f, 0.f, 0.f);
            int gm = m0 + row, gn = n0 + row;
            if (gm < Tt) va = *(const float4*)&Ag[(size_t)gm * Dd + k0 + q * 4];
            if (gn < Tt) vb = *(const float4*)&Bg[(size_t)gn * Dd + k0 + q * 4];
            As[q * 4 + 0][row] = va.x; As[q * 4 + 1][row] = va.y;
            As[q * 4 + 2][row] = va.z; As[q * 4 + 3][row] = va.w;
            Bs[q * 4 + 0][row] = vb.x; Bs[q * 4 + 1][row] = vb.y;
            Bs[q * 4 + 2][row] = vb.z; Bs[q * 4 + 3][row] = vb.w;
        }
        __syncthreads();
        #pragma unroll
        for (int k = 0; k < 16; k++) {
            float a[8], bb[8];
            *(float4*)&a[0]  = *(const float4*)&As[k][ty * 8];
            *(float4*)&a[4]  = *(const float4*)&As[k][ty * 8 + 4];
            *(float4*)&bb[0] = *(const float4*)&Bs[k][tx * 8];
            *(float4*)&bb[4] = *(const float4*)&Bs[k][tx * 8 + 4];
            #pragma unroll
            for (int i = 0; i < 8; i++)
                #pragma unroll
                for (int j = 0; j < 8; j++)
                    acc[i][j] = fmaf(a[i], bb[j], acc[i][j]);
        }
        __syncthreads();
    }

    float* __restrict__ Pg = g_P + (size_t)hb * Tt * Tt;
    #pragma unroll
    for (int i = 0; i < 8; i++) {
        int m = m0 + ty * 8 + i;
        if (m >= Tt) continue;
        #pragma unroll
        for (int j = 0; j < 8; j++) {
            int n = n0 + tx * 8 + j;
            if (n < Tt) Pg[(size_t)m * Tt + n] = acc[i][j] * 0.0625f;
        }
    }
}

// ---------------------------------------------------------------------------
// Kernel 3: row softmax in place over g_P, one block per row
// ---------------------------------------------------------------------------
__global__ void __launch_bounds__(256) softmax_kernel()
{
    __shared__ float red[8];
    size_t row = blockIdx.x;
    float* __restrict__ p = g_P + row * Tt;
    int tid = threadIdx.x;

    float v[4];
    int cnt = 0;
    float m = -1e30f;
    for (int i = tid; i < Tt; i += 256) {
        v[cnt] = p[i];
        m = fmaxf(m, v[cnt]);
        cnt++;
    }
    #pragma unroll
    for (int o = 16; o > 0; o >>= 1) m = fmaxf(m, __shfl_xor_sync(0xffffffffu, m, o));
    if ((tid & 31) == 0) red[tid >> 5] = m;
    __syncthreads();
    m = red[0];
    #pragma unroll
    for (int w = 1; w < 8; w++) m = fmaxf(m, red[w]);
    __syncthreads();

    float s = 0.f;
    for (int i = 0; i < cnt; i++) { v[i] = __expf(v[i] - m); s += v[i]; }
    #pragma unroll
    for (int o = 16; o > 0; o >>= 1) s += __shfl_xor_sync(0xffffffffu, s, o);
    if ((tid & 31) == 0) red[tid >> 5] = s;
    __syncthreads();
    s = 0.f;
    #pragma unroll
    for (int w = 0; w < 8; w++) s += red[w];

    float inv = 1.f / s;
    cnt = 0;
    for (int i = tid; i < Tt; i += 256) { p[i] = v[cnt] * inv; cnt++; }
}

// ---------------------------------------------------------------------------
// Kernel 4: A = P @ V, batched over hb. 128x128 tile, BK=8.
// ---------------------------------------------------------------------------
__global__ void __launch_bounds__(256) gemm_pv_kernel()
{
    __shared__ float As[8][132];
    __shared__ float Bs[8][128];

    int hb = blockIdx.z;
    int m0 = blockIdx.y * 128;
    int n0 = blockIdx.x * 128;
    int tid = threadIdx.x;
    int tx = tid & 15, ty = tid >> 4;

    const float* __restrict__ Ag = g_P + (size_t)hb * Tt * Tt;
    const float* __restrict__ Bg = g_V + (size_t)hb * Tt * DV;

    float acc[8][8];
    #pragma unroll
    for (int i = 0; i < 8; i++)
        #pragma unroll
        for (int j = 0; j < 8; j++) acc[i][j] = 0.f;

    int arow = tid >> 1, aq = tid & 1;
    int bk = tid >> 5, bq = tid & 31;

    for (int k0 = 0; k0 < Tt; k0 += 8) {
        {
            int gm = m0 + arow;
            float4 va = make_float4(0.f, 0.f, 0.f, 0.f);
            if (gm < Tt) va = *(const float4*)&Ag[(size_t)gm * Tt + k0 + aq * 4];
            As[aq * 4 + 0][arow] = va.x; As[aq * 4 + 1][arow] = va.y;
            As[aq * 4 + 2][arow] = va.z; As[aq * 4 + 3][arow] = va.w;
            *(float4*)&Bs[bk][bq * 4] =
                *(const float4*)&Bg[(size_t)(k0 + bk) * DV + n0 + bq * 4];
        }
        __syncthreads();
        #pragma unroll
        for (int k = 0; k < 8; k++) {
            float a[8], bb[8];
            *(float4*)&a[0]  = *(const float4*)&As[k][ty * 8];
            *(float4*)&a[4]  = *(const float4*)&As[k][ty * 8 + 4];
            *(float4*)&bb[0] = *(const float4*)&Bs[k][tx * 8];
            *(float4*)&bb[4] = *(const float4*)&Bs[k][tx * 8 + 4];
            #pragma unroll
            for (int i = 0; i < 8; i++)
                #pragma unroll
                for (int j = 0; j < 8; j++)
                    acc[i][j] = fmaf(a[i], bb[j], acc[i][j]);
        }
        __syncthreads();
    }

    float* __restrict__ Og = g_A + (size_t)hb * Tt * DV;
    #pragma unroll
    for (int i = 0; i < 8; i++) {
        int m = m0 + ty * 8 + i;
        if (m >= Tt) continue;
        *(float4*)&Og[(size_t)m * DV + n0 + tx * 8]     = *(float4*)&acc[i][0];
        *(float4*)&Og[(size_t)m * DV + n0 + tx * 8 + 4] = *(float4*)&acc[i][4];
    }
}

// ---------------------------------------------------------------------------
// Kernel 5: output 1x1 conv + PReLU + ChanFreqNorm + residual
// block = one (b, t); 256 threads: tid -> (co = tid>>6 in 0..3, f = tid&63)
// ---------------------------------------------------------------------------
__global__ void __launch_bounds__(256) out_kernel(
    const float* __restrict__ x,
    const float* __restrict__ lw, const float* __restrict__ lb,
    const float* __restrict__ la, const float* __restrict__ lg,
    const float* __restrict__ lbe,
    float* __restrict__ out)
{
    __shared__ float xs[Cc * Ff];    // xo tile, c-major: xs[c*64+f]
    __shared__ float lws[Cc * Cc];   // l_w[o][c]
    __shared__ float reds[8], redss[8];

    int bid = blockIdx.x;
    int b = bid / Tt, t = bid % Tt;
    int tid = threadIdx.x;

    // gather xo[b, :, t, :] from g_A: c = h*CV + cv, contiguous per head
    for (int h = 0; h < Hh; h++) {
        size_t base = ((size_t)(h * Bb + b) * Tt + t) * DV;
        for (int i = tid; i < DV; i += 256) xs[h * DV + i] = g_A[base + i];
    }
    for (int i = tid; i < Cc * Cc; i += 256) lws[i] = lw[i];
    __syncthreads();

    int f = tid & 63, co = tid >> 6;
    float alpha = la[0];

    float yv[16];
    #pragma unroll
    for (int j = 0; j < 16; j++) yv[j] = lb[co * 16 + j];

    for (int ci = 0; ci < Cc; ci++) {
        float xv = xs[ci * Ff + f];
        #pragma unroll
        for (int j = 0; j < 16; j++)
            yv[j] = fmaf(lws[(co * 16 + j) * Cc + ci], xv, yv[j]);
    }

    float s = 0.f, ss = 0.f;
    #pragma unroll
    for (int j = 0; j < 16; j++) {
        float y = yv[j];
        y = y > 0.f ? y : alpha * y;
        yv[j] = y;
        s += y; ss += y * y;
    }

    // block-wide reduction over all 4096 values
    #pragma unroll
    for (int o = 16; o > 0; o >>= 1) {
        s  += __shfl_xor_sync(0xffffffffu, s,  o);
        ss += __shfl_xor_sync(0xffffffffu, ss, o);
    }
    if ((tid & 31) == 0) { reds[tid >> 5] = s; redss[tid >> 5] = ss; }
    __syncthreads();
    s = 0.f; ss = 0.f;
    #pragma unroll
    for (int w = 0; w < 8; w++) { s += reds[w]; ss += redss[w]; }

    float mu  = s * (1.f / 4096.f);
    float var = ss * (1.f / 4096.f) - mu * mu;
    float inv = 1.f / (sqrtf(fmaxf(var, 0.f)) + EPSV);

    #pragma unroll
    for (int j = 0; j < 16; j++) {
        int c = co * 16 + j;
        size_t oi = (((size_t)b * Cc + c) * Tt + t) * Ff + f;
        out[oi] = (yv[j] - mu) * inv * lg[c * Ff + f] + lbe[c * Ff + f] + x[oi];
    }
}

// ---------------------------------------------------------------------------
extern "C" void kernel_launch(void* const* d_in, const int* in_sizes, int n_in,
                              void* d_out, int out_size)
{
    const float* x    = (const float*)d_in[0];
    const float* q_w  = (const float*)d_in[1];
    const float* q_b  = (const float*)d_in[2];
    const float* q_a  = (const float*)d_in[3];
    const float* q_g  = (const float*)d_in[4];
    const float* q_be = (const float*)d_in[5];
    const float* k_w  = (const float*)d_in[6];
    const float* k_b  = (const float*)d_in[7];
    const float* k_a  = (const float*)d_in[8];
    const float* k_g  = (const float*)d_in[9];
    const float* k_be = (const float*)d_in[10];
    const float* v_w  = (const float*)d_in[11];
    const float* v_b  = (const float*)d_in[12];
    const float* v_a  = (const float*)d_in[13];
    const float* v_g  = (const float*)d_in[14];
    const float* v_be = (const float*)d_in[15];
    const float* l_w  = (const float*)d_in[16];
    const float* l_b  = (const float*)d_in[17];
    const float* l_a  = (const float*)d_in[18];
    const float* l_g  = (const float*)d_in[19];
    const float* l_be = (const float*)d_in[20];
    float* out = (float*)d_out;

    qkv_kernel<<<Bb * Tt, 256>>>(x,
        q_w, q_b, q_a, q_g, q_be,
        k_w, k_b, k_a, k_g, k_be,
        v_w, v_b, v_a, v_g, v_be);

    gemm_qk_kernel<<<dim3(8, 8, HB), 256>>>();

    softmax_kernel<<<HB * Tt, 256>>>();

    gemm_pv_kernel<<<dim3(DV / 128, 8, HB), 256>>>();

    out_kernel<<<Bb * Tt, 256>>>(x, l_w, l_b, l_a, l_g, l_be, out);
}

// round 2
// speedup vs baseline: 2.1245x; 2.1245x over previous
#include <cuda_runtime.h>
#include <math.h>
#include <stdint.h>

#define EPSV 1e-5f

// Problem constants
constexpr int Bb  = 8;
constexpr int Cc  = 64;
constexpr int Tt  = 1000;
constexpr int Ff  = 64;
constexpr int Hh  = 4;
constexpr int HSs = 4;
constexpr int CVv = 16;
constexpr int Dd  = HSs * Ff;   // 256
constexpr int DV  = CVv * Ff;   // 1024
constexpr int HB  = Hh * Bb;    // 32
constexpr int Tp  = 1024;       // padded T (zero-filled tail)

// Static device scratch (zero-initialized; padded regions stay zero forever)
__device__ float g_Q[HB * Tp * Dd];        // 33.5 MB
__device__ float g_K[HB * Tp * Dd];        // 33.5 MB
__device__ float g_V[HB * Tp * DV];        // 134 MB   V[k=t][n]
__device__ float g_P[HB * Tp * Tp];        // 134 MB   P[m][k], cols>=1000 zeroed
__device__ float g_A[HB * Tp * DV];        // 134 MB

// ---------------------------------------------------------------------------
__device__ __forceinline__ float round_tf32(float x) {
    uint32_t u;
    asm("cvt.rna.tf32.f32 %0, %1;" : "=r"(u) : "f"(x));
    return __uint_as_float(u);
}

__device__ __forceinline__ void mma_tf32(float* c, const uint32_t* a, const uint32_t* b) {
    asm volatile(
        "mma.sync.aligned.m16n8k8.row.col.f32.tf32.tf32.f32 "
        "{%0,%1,%2,%3}, {%4,%5,%6,%7}, {%8,%9}, {%0,%1,%2,%3};"
        : "+f"(c[0]), "+f"(c[1]), "+f"(c[2]), "+f"(c[3])
        : "r"(a[0]), "r"(a[1]), "r"(a[2]), "r"(a[3]), "r"(b[0]), "r"(b[1]));
}

// swizzle: physical column = col ^ (((k + (k>>2)) & 3) << 3)
__device__ __forceinline__ int swz(int k) { return ((k + (k >> 2)) & 3) << 3; }

// ---------------------------------------------------------------------------
// group reduce: sum & sumsq over 64-thread group (2 aligned warps)
// ---------------------------------------------------------------------------
__device__ __forceinline__ void group_reduce64(float& s, float& ss, int tid,
                                               float* reds, float* redss) {
    #pragma unroll
    for (int o = 16; o > 0; o >>= 1) {
        s  += __shfl_xor_sync(0xffffffffu, s,  o);
        ss += __shfl_xor_sync(0xffffffffu, ss, o);
    }
    int warp = tid >> 5;
    if ((tid & 31) == 0) { reds[warp] = s; redss[warp] = ss; }
    __syncthreads();
    int h = tid >> 6;
    s  = reds[2 * h]  + reds[2 * h + 1];
    ss = redss[2 * h] + redss[2 * h + 1];
    __syncthreads();
}

// ---------------------------------------------------------------------------
// Kernel 1: QKV 1x1 conv + bias + PReLU + ChanFreqNorm; tf32-rounded outputs
// block = one (b, t); 256 threads: tid -> (h = tid>>6, f = tid&63)
// ---------------------------------------------------------------------------
__global__ void __launch_bounds__(256) qkv_kernel(
    const float* __restrict__ x,
    const float* __restrict__ qw, const float* __restrict__ qb,
    const float* __restrict__ qa, const float* __restrict__ qg,
    const float* __restrict__ qbe,
    const float* __restrict__ kw, const float* __restrict__ kb,
    const float* __restrict__ ka, const float* __restrict__ kg,
    const float* __restrict__ kbe,
    const float* __restrict__ vw, const float* __restrict__ vb,
    const float* __restrict__ va, const float* __restrict__ vg,
    const float* __restrict__ vbe)
{
    __shared__ float xs[Cc * Ff];
    __shared__ float qws[Hh * HSs * Cc];
    __shared__ float kws[Hh * HSs * Cc];
    __shared__ float vws[Hh * CVv * Cc];
    __shared__ float reds[8], redss[8];

    int bid = blockIdx.x;
    int b = bid / Tt, t = bid % Tt;
    int tid = threadIdx.x;

    for (int i = tid; i < Cc * Ff; i += 256) {
        int c = i >> 6, f = i & 63;
        xs[i] = x[(((size_t)b * Cc + c) * Tt + t) * Ff + f];
    }
    for (int i = tid; i < Hh * HSs * Cc; i += 256) { qws[i] = qw[i]; kws[i] = kw[i]; }
    for (int i = tid; i < Hh * CVv * Cc; i += 256) vws[i] = vw[i];
    __syncthreads();

    int h = tid >> 6, f = tid & 63;

    float qv[HSs], kv[HSs], vv[CVv];
    #pragma unroll
    for (int i = 0; i < HSs; i++) { qv[i] = 0.f; kv[i] = 0.f; }
    #pragma unroll
    for (int i = 0; i < CVv; i++) vv[i] = 0.f;

    for (int c = 0; c < Cc; c++) {
        float xv = xs[c * Ff + f];
        #pragma unroll
        for (int i = 0; i < HSs; i++) {
            qv[i] = fmaf(qws[(h * HSs + i) * Cc + c], xv, qv[i]);
            kv[i] = fmaf(kws[(h * HSs + i) * Cc + c], xv, kv[i]);
        }
        #pragma unroll
        for (int i = 0; i < CVv; i++)
            vv[i] = fmaf(vws[(h * CVv + i) * Cc + c], xv, vv[i]);
    }

    int hb = h * Bb + b;

    // Q branch
    {
        float alpha = qa[h];
        float s = 0.f, ss = 0.f;
        #pragma unroll
        for (int i = 0; i < HSs; i++) {
            float y = qv[i] + qb[h * HSs + i];
            y = y > 0.f ? y : alpha * y;
            qv[i] = y;
            s += y; ss += y * y;
        }
        group_reduce64(s, ss, tid, reds, redss);
        float mu  = s * (1.f / (HSs * Ff));
        float var = ss * (1.f / (HSs * Ff)) - mu * mu;
        float inv = 1.f / (sqrtf(fmaxf(var, 0.f)) + EPSV);
        size_t base = ((size_t)hb * Tp + t) * Dd;
        #pragma unroll
        for (int i = 0; i < HSs; i++) {
            int gi = (h * HSs + i) * Ff + f;
            g_Q[base + i * Ff + f] = round_tf32((qv[i] - mu) * inv * qg[gi] + qbe[gi]);
        }
    }

    // K branch
    {
        float alpha = ka[h];
        float s = 0.f, ss = 0.f;
        #pragma unroll
        for (int i = 0; i < HSs; i++) {
            float y = kv[i] + kb[h * HSs + i];
            y = y > 0.f ? y : alpha * y;
            kv[i] = y;
            s += y; ss += y * y;
        }
        group_reduce64(s, ss, tid, reds, redss);
        float mu  = s * (1.f / (HSs * Ff));
        float var = ss * (1.f / (HSs * Ff)) - mu * mu;
        float inv = 1.f / (sqrtf(fmaxf(var, 0.f)) + EPSV);
        size_t base = ((size_t)hb * Tp + t) * Dd;
        #pragma unroll
        for (int i = 0; i < HSs; i++) {
            int gi = (h * HSs + i) * Ff + f;
            g_K[base + i * Ff + f] = round_tf32((kv[i] - mu) * inv * kg[gi] + kbe[gi]);
        }
    }

    // V branch
    {
        float alpha = va[h];
        float s = 0.f, ss = 0.f;
        #pragma unroll
        for (int i = 0; i < CVv; i++) {
            float y = vv[i] + vb[h * CVv + i];
            y = y > 0.f ? y : alpha * y;
            vv[i] = y;
            s += y; ss += y * y;
        }
        group_reduce64(s, ss, tid, reds, redss);
        float mu  = s * (1.f / (CVv * Ff));
        float var = ss * (1.f / (CVv * Ff)) - mu * mu;
        float inv = 1.f / (sqrtf(fmaxf(var, 0.f)) + EPSV);
        size_t base = ((size_t)hb * Tp + t) * DV;
        #pragma unroll
        for (int i = 0; i < CVv; i++) {
            int gi = (h * CVv + i) * Ff + f;
            g_V[base + i * Ff + f] = round_tf32((vv[i] - mu) * inv * vg[gi] + vbe[gi]);
        }
    }
}

// ---------------------------------------------------------------------------
// Kernel 2: scores = (Q @ K^T) * 0.0625 via tf32 tensor cores
// block: 128x128 tile, BK=16, 256 threads (8 warps, warp = 64x32)
// no predicates: buffers padded to 1024 rows (zero tail)
// ---------------------------------------------------------------------------
__global__ void __launch_bounds__(256, 2) gemm_qk_tc()
{
    __shared__ float As[2][16][128];
    __shared__ float Bs[2][16][128];

    int hb = blockIdx.z;
    int m0 = blockIdx.y * 128, n0 = blockIdx.x * 128;
    int tid = threadIdx.x;
    const float* __restrict__ Ag = g_Q + (size_t)hb * Tp * Dd;
    const float* __restrict__ Bg = g_K + (size_t)hb * Tp * Dd;

    int lane = tid & 31, w = tid >> 5;
    int wm = (w & 1) * 64, wn = (w >> 1) * 32;
    int r = lane >> 2, cq = lane & 3;

    int lrow = tid >> 2;        // 0..63
    int lc4  = (tid & 3) * 4;   // 0,4,8,12

    float acc[4][4][4];
    #pragma unroll
    for (int i = 0; i < 4; i++)
        #pragma unroll
        for (int j = 0; j < 4; j++)
            #pragma unroll
            for (int q = 0; q < 4; q++) acc[i][j][q] = 0.f;

    float4 ra[2], rb[2];
    #pragma unroll
    for (int l = 0; l < 2; l++) {
        ra[l] = *(const float4*)&Ag[(size_t)(m0 + lrow + 64 * l) * Dd + lc4];
        rb[l] = *(const float4*)&Bg[(size_t)(n0 + lrow + 64 * l) * Dd + lc4];
    }
    #pragma unroll
    for (int l = 0; l < 2; l++) {
        int m = lrow + 64 * l;
        const float* pa = (const float*)&ra[l];
        const float* pb = (const float*)&rb[l];
        #pragma unroll
        for (int j = 0; j < 4; j++) {
            int k = lc4 + j;
            int sx = swz(k);
            As[0][k][m ^ sx] = pa[j];
            Bs[0][k][m ^ sx] = pb[j];
        }
    }
    __syncthreads();

    const int KT = Dd / 16;   // 16
    for (int kt = 0; kt < KT; kt++) {
        int cur = kt & 1;
        if (kt + 1 < KT) {
            int k0 = (kt + 1) * 16;
            #pragma unroll
            for (int l = 0; l < 2; l++) {
                ra[l] = *(const float4*)&Ag[(size_t)(m0 + lrow + 64 * l) * Dd + k0 + lc4];
                rb[l] = *(const float4*)&Bg[(size_t)(n0 + lrow + 64 * l) * Dd + k0 + lc4];
            }
        }
        #pragma unroll
        for (int kk = 0; kk < 16; kk += 8) {
            int klo = kk + cq, khi = klo + 4;
            int slo = swz(klo), shi = swz(khi);
            const float* Alo = As[cur][klo];
            const float* Ahi = As[cur][khi];
            const float* Blo = Bs[cur][klo];
            const float* Bhi = Bs[cur][khi];
            uint32_t af[4][4], bf[4][2];
            #pragma unroll
            for (int mi = 0; mi < 4; mi++) {
                int m = wm + mi * 16 + r;
                af[mi][0] = __float_as_uint(Alo[m ^ slo]);
                af[mi][1] = __float_as_uint(Alo[(m + 8) ^ slo]);
                af[mi][2] = __float_as_uint(Ahi[m ^ shi]);
                af[mi][3] = __float_as_uint(Ahi[(m + 8) ^ shi]);
            }
            #pragma unroll
            for (int ni = 0; ni < 4; ni++) {
                int n = wn + ni * 8 + r;
                bf[ni][0] = __float_as_uint(Blo[n ^ slo]);
                bf[ni][1] = __float_as_uint(Bhi[n ^ shi]);
            }
            #pragma unroll
            for (int mi = 0; mi < 4; mi++)
                #pragma unroll
                for (int ni = 0; ni < 4; ni++)
                    mma_tf32(acc[mi][ni], af[mi], bf[ni]);
        }
        if (kt + 1 < KT) {
            int nb = (kt + 1) & 1;
            #pragma unroll
            for (int l = 0; l < 2; l++) {
                int m = lrow + 64 * l;
                const float* pa = (const float*)&ra[l];
                const float* pb = (const float*)&rb[l];
                #pragma unroll
                for (int j = 0; j < 4; j++) {
                    int k = lc4 + j;
                    int sx = swz(k);
                    As[nb][k][m ^ sx] = pa[j];
                    Bs[nb][k][m ^ sx] = pb[j];
                }
            }
        }
        __syncthreads();
    }

    float* __restrict__ Pg = g_P + (size_t)hb * Tp * Tp;
    #pragma unroll
    for (int mi = 0; mi < 4; mi++)
        #pragma unroll
        for (int ni = 0; ni < 4; ni++) {
            int row = m0 + wm + mi * 16 + r;
            int col = n0 + wn + ni * 8 + 2 * cq;
            float2 v0 = make_float2(acc[mi][ni][0] * 0.0625f, acc[mi][ni][1] * 0.0625f);
            float2 v1 = make_float2(acc[mi][ni][2] * 0.0625f, acc[mi][ni][3] * 0.0625f);
            *(float2*)&Pg[(size_t)row * Tp + col] = v0;
            *(float2*)&Pg[(size_t)(row + 8) * Tp + col] = v1;
        }
}

// ---------------------------------------------------------------------------
// Kernel 3: row softmax in place over g_P; writes tf32-rounded probs,
// zeros padded cols [1000,1024)
// ---------------------------------------------------------------------------
__global__ void __launch_bounds__(256) softmax_kernel()
{
    __shared__ float red[8];
    int hb = blockIdx.x / Tt;
    int mrow = blockIdx.x % Tt;
    float* __restrict__ p = g_P + ((size_t)hb * Tp + mrow) * Tp;
    int tid = threadIdx.x;

    float v[4];
    int cnt = 0;
    float m = -1e30f;
    for (int i = tid; i < Tt; i += 256) {
        v[cnt] = p[i];
        m = fmaxf(m, v[cnt]);
        cnt++;
    }
    #pragma unroll
    for (int o = 16; o > 0; o >>= 1) m = fmaxf(m, __shfl_xor_sync(0xffffffffu, m, o));
    if ((tid & 31) == 0) red[tid >> 5] = m;
    __syncthreads();
    m = red[0];
    #pragma unroll
    for (int wv = 1; wv < 8; wv++) m = fmaxf(m, red[wv]);
    __syncthreads();

    float s = 0.f;
    for (int i = 0; i < cnt; i++) { v[i] = __expf(v[i] - m); s += v[i]; }
    #pragma unroll
    for (int o = 16; o > 0; o >>= 1) s += __shfl_xor_sync(0xffffffffu, s, o);
    if ((tid & 31) == 0) red[tid >> 5] = s;
    __syncthreads();
    s = 0.f;
    #pragma unroll
    for (int wv = 0; wv < 8; wv++) s += red[wv];

    float inv = 1.f / s;
    cnt = 0;
    for (int i = tid; i < Tt; i += 256) { p[i] = round_tf32(v[cnt] * inv); cnt++; }
    for (int i = Tt + tid; i < Tp; i += 256) p[i] = 0.f;
}

// ---------------------------------------------------------------------------
// Kernel 4: A = P @ V via tf32 tensor cores. K=1024, BK=16.
// A transpose-loaded; B (=V[k][n]) copied directly.
// ---------------------------------------------------------------------------
__global__ void __launch_bounds__(256, 2) gemm_pv_tc()
{
    __shared__ float As[2][16][128];
    __shared__ float Bs[2][16][128];

    int hb = blockIdx.z;
    int m0 = blockIdx.y * 128, n0 = blockIdx.x * 128;
    int tid = threadIdx.x;
    const float* __restrict__ Ag = g_P + (size_t)hb * Tp * Tp;
    const float* __restrict__ Bg = g_V + (size_t)hb * Tp * DV;

    int lane = tid & 31, w = tid >> 5;
    int wm = (w & 1) * 64, wn = (w >> 1) * 32;
    int r = lane >> 2, cq = lane & 3;

    int lrow = tid >> 2;        // A-load: 0..63
    int lc4  = (tid & 3) * 4;   // A-load k chunk
    int bn4  = tid & 31;        // B-load: float4 col
    int bkr  = tid >> 5;        // B-load: k row 0..7

    float acc[4][4][4];
    #pragma unroll
    for (int i = 0; i < 4; i++)
        #pragma unroll
        for (int j = 0; j < 4; j++)
            #pragma unroll
            for (int q = 0; q < 4; q++) acc[i][j][q] = 0.f;

    float4 ra[2], rb[2];
    #pragma unroll
    for (int l = 0; l < 2; l++) {
        ra[l] = *(const float4*)&Ag[(size_t)(m0 + lrow + 64 * l) * Tp + lc4];
        rb[l] = *(const float4*)&Bg[(size_t)(bkr + 8 * l) * DV + n0 + bn4 * 4];
    }
    #pragma unroll
    for (int l = 0; l < 2; l++) {
        int m = lrow + 64 * l;
        const float* pa = (const float*)&ra[l];
        #pragma unroll
        for (int j = 0; j < 4; j++) {
            int k = lc4 + j;
            As[0][k][m ^ swz(k)] = pa[j];
        }
        int kb = bkr + 8 * l;
        *(float4*)&Bs[0][kb][(bn4 * 4) ^ swz(kb)] = rb[l];
    }
    __syncthreads();

    const int KT = Tp / 16;   // 64
    for (int kt = 0; kt < KT; kt++) {
        int cur = kt & 1;
        if (kt + 1 < KT) {
            int k0 = (kt + 1) * 16;
            #pragma unroll
            for (int l = 0; l < 2; l++) {
                ra[l] = *(const float4*)&Ag[(size_t)(m0 + lrow + 64 * l) * Tp + k0 + lc4];
                rb[l] = *(const float4*)&Bg[(size_t)(k0 + bkr + 8 * l) * DV + n0 + bn4 * 4];
            }
        }
        #pragma unroll
        for (int kk = 0; kk < 16; kk += 8) {
            int klo = kk + cq, khi = klo + 4;
            int slo = swz(klo), shi = swz(khi);
            const float* Alo = As[cur][klo];
            const float* Ahi = As[cur][khi];
            const float* Blo = Bs[cur][klo];
            const float* Bhi = Bs[cur][khi];
            uint32_t af[4][4], bf[4][2];
            #pragma unroll
            for (int mi = 0; mi < 4; mi++) {
                int m = wm + mi * 16 + r;
                af[mi][0] = __float_as_uint(Alo[m ^ slo]);
                af[mi][1] = __float_as_uint(Alo[(m + 8) ^ slo]);
                af[mi][2] = __float_as_uint(Ahi[m ^ shi]);
                af[mi][3] = __float_as_uint(Ahi[(m + 8) ^ shi]);
            }
            #pragma unroll
            for (int ni = 0; ni < 4; ni++) {
                int n = wn + ni * 8 + r;
                bf[ni][0] = __float_as_uint(Blo[n ^ slo]);
                bf[ni][1] = __float_as_uint(Bhi[n ^ shi]);
            }
            #pragma unroll
            for (int mi = 0; mi < 4; mi++)
                #pragma unroll
                for (int ni = 0; ni < 4; ni++)
                    mma_tf32(acc[mi][ni], af[mi], bf[ni]);
        }
        if (kt + 1 < KT) {
            int nb = (kt + 1) & 1;
            #pragma unroll
            for (int l = 0; l < 2; l++) {
                int m = lrow + 64 * l;
                const float* pa = (const float*)&ra[l];
                #pragma unroll
                for (int j = 0; j < 4; j++) {
                    int k = lc4 + j;
                    As[nb][k][m ^ swz(k)] = pa[j];
                }
                int kb = bkr + 8 * l;
                *(float4*)&Bs[nb][kb][(bn4 * 4) ^ swz(kb)] = rb[l];
            }
        }
        __syncthreads();
    }

    float* __restrict__ Og = g_A + (size_t)hb * Tp * DV;
    #pragma unroll
    for (int mi = 0; mi < 4; mi++)
        #pragma unroll
        for (int ni = 0; ni < 4; ni++) {
            int row = m0 + wm + mi * 16 + r;
            int col = n0 + wn + ni * 8 + 2 * cq;
            *(float2*)&Og[(size_t)row * DV + col] =
                make_float2(acc[mi][ni][0], acc[mi][ni][1]);
            *(float2*)&Og[(size_t)(row + 8) * DV + col] =
                make_float2(acc[mi][ni][2], acc[mi][ni][3]);
        }
}

// ---------------------------------------------------------------------------
// Kernel 5: output 1x1 conv + PReLU + ChanFreqNorm + residual
// ---------------------------------------------------------------------------
__global__ void __launch_bounds__(256) out_kernel(
    const float* __restrict__ x,
    const float* __restrict__ lw, const float* __restrict__ lb,
    const float* __restrict__ la, const float* __restrict__ lg,
    const float* __restrict__ lbe,
    float* __restrict__ out)
{
    __shared__ float xs[Cc * Ff];
    __shared__ float lws[Cc * Cc];
    __shared__ float reds[8], redss[8];

    int bid = blockIdx.x;
    int b = bid / Tt, t = bid % Tt;
    int tid = threadIdx.x;

    for (int h = 0; h < Hh; h++) {
        size_t base = ((size_t)(h * Bb + b) * Tp + t) * DV;
        for (int i = tid; i < DV; i += 256) xs[h * DV + i] = g_A[base + i];
    }
    for (int i = tid; i < Cc * Cc; i += 256) lws[i] = lw[i];
    __syncthreads();

    int f = tid & 63, co = tid >> 6;
    float alpha = la[0];

    float yv[16];
    #pragma unroll
    for (int j = 0; j < 16; j++) yv[j] = lb[co * 16 + j];

    for (int ci = 0; ci < Cc; ci++) {
        float xv = xs[ci * Ff + f];
        #pragma unroll
        for (int j = 0; j < 16; j++)
            yv[j] = fmaf(lws[(co * 16 + j) * Cc + ci], xv, yv[j]);
    }

    float s = 0.f, ss = 0.f;
    #pragma unroll
    for (int j = 0; j < 16; j++) {
        float y = yv[j];
        y = y > 0.f ? y : alpha * y;
        yv[j] = y;
        s += y; ss += y * y;
    }

    #pragma unroll
    for (int o = 16; o > 0; o >>= 1) {
        s  += __shfl_xor_sync(0xffffffffu, s,  o);
        ss += __shfl_xor_sync(0xffffffffu, ss, o);
    }
    if ((tid & 31) == 0) { reds[tid >> 5] = s; redss[tid >> 5] = ss; }
    __syncthreads();
    s = 0.f; ss = 0.f;
    #pragma unroll
    for (int wv = 0; wv < 8; wv++) { s += reds[wv]; ss += redss[wv]; }

    float mu  = s * (1.f / 4096.f);
    float var = ss * (1.f / 4096.f) - mu * mu;
    float inv = 1.f / (sqrtf(fmaxf(var, 0.f)) + EPSV);

    #pragma unroll
    for (int j = 0; j < 16; j++) {
        int c = co * 16 + j;
        size_t oi = (((size_t)b * Cc + c) * Tt + t) * Ff + f;
        out[oi] = (yv[j] - mu) * inv * lg[c * Ff + f] + lbe[c * Ff + f] + x[oi];
    }
}

// ---------------------------------------------------------------------------
extern "C" void kernel_launch(void* const* d_in, const int* in_sizes, int n_in,
                              void* d_out, int out_size)
{
    const float* x    = (const float*)d_in[0];
    const float* q_w  = (const float*)d_in[1];
    const float* q_b  = (const float*)d_in[2];
    const float* q_a  = (const float*)d_in[3];
    const float* q_g  = (const float*)d_in[4];
    const float* q_be = (const float*)d_in[5];
    const float* k_w  = (const float*)d_in[6];
    const float* k_b  = (const float*)d_in[7];
    const float* k_a  = (const float*)d_in[8];
    const float* k_g  = (const float*)d_in[9];
    const float* k_be = (const float*)d_in[10];
    const float* v_w  = (const float*)d_in[11];
    const float* v_b  = (const float*)d_in[12];
    const float* v_a  = (const float*)d_in[13];
    const float* v_g  = (const float*)d_in[14];
    const float* v_be = (const float*)d_in[15];
    const float* l_w  = (const float*)d_in[16];
    const float* l_b  = (const float*)d_in[17];
    const float* l_a  = (const float*)d_in[18];
    const float* l_g  = (const float*)d_in[19];
    const float* l_be = (const float*)d_in[20];
    float* out = (float*)d_out;

    qkv_kernel<<<Bb * Tt, 256>>>(x,
        q_w, q_b, q_a, q_g, q_be,
        k_w, k_b, k_a, k_g, k_be,
        v_w, v_b, v_a, v_g, v_be);

    gemm_qk_tc<<<dim3(8, 8, HB), 256>>>();

    softmax_kernel<<<HB * Tt, 256>>>();

    gemm_pv_tc<<<dim3(DV / 128, 8, HB), 256>>>();

    out_kernel<<<Bb * Tt, 256>>>(x, l_w, l_b, l_a, l_g, l_be, out);
}